// round 12
// baseline (speedup 1.0000x reference)
#include <cuda_runtime.h>
#include <cstdint>

#define N_NODES 50000
#define IN_FEAT 512
#define OUT_FEAT 256
#define N_EDGES 1600000
#define ALPHA 0.2f

#define NODE_CHUNK 8       // nodes stolen per warp
#define EDGE_CHUNK 128     // float4-groups stolen per warp (= 512 edges)

// Scratch (allocation-free rule: __device__ globals).
__device__ float4 g_w_src4[IN_FEAT / 4];
__device__ float4 g_w_tgt4[IN_FEAT / 4];
__device__ float g_s_src[N_NODES];
__device__ float g_s_tgt[N_NODES];

// Monotonic-ticket grid barrier (no reset; safe across graph replays).
__device__ unsigned g_bar = 0;
// Work-stealing counters: reset each replay before the first barrier.
__device__ unsigned g_node_ctr = 0;
__device__ unsigned g_edge_ctr = 0;

__device__ __forceinline__ float dot4(float4 a, float4 b) {
    return a.x * b.x + a.y * b.y + a.z * b.z + a.w * b.w;
}

__device__ __forceinline__ void grid_sync(unsigned nblocks) {
    __syncthreads();
    if (threadIdx.x == 0) {
        __threadfence();
        unsigned ticket = atomicAdd(&g_bar, 1u);
        unsigned target = (ticket / nblocks + 1u) * nblocks;
        while (*(volatile unsigned*)&g_bar < target) { }
        __threadfence();
    }
    __syncthreads();
}

__device__ __forceinline__ void prefetch_l2(const void* p) {
    asm volatile("prefetch.global.L2 [%0];" :: "l"(p));
}

// ---------------------------------------------------------------------------
// Fused persistent kernel: A -> barrier -> B (stealing + edge prefetch)
// -> barrier -> C (stealing).
// ---------------------------------------------------------------------------
__global__ __launch_bounds__(256) void fused_gat_kernel(
    const float* __restrict__ h,
    const int*   __restrict__ edge_list,
    const float* __restrict__ W,
    const float* __restrict__ attn_w,
    float*       __restrict__ out,
    int nblocks)
{
    __shared__ float4 sh_ws[IN_FEAT / 4];
    __shared__ float4 sh_wt[IN_FEAT / 4];

    const int tid  = threadIdx.x;
    const int lane = tid & 31;
    const int wid  = tid >> 5;                    // 0..7
    const int gw   = blockIdx.x * 8 + wid;        // global warp id

    // Reset stealing counters for this replay (visible after first barrier).
    if (blockIdx.x == 0 && tid == 0) {
        g_node_ctr = 0;
        g_edge_ctr = 0;
    }

    // ---------------- Phase A: w_src = W @ a_src, w_tgt = W @ a_tgt --------
    if (gw < IN_FEAT) {
        const float4* wrow4 = reinterpret_cast<const float4*>(W + (size_t)gw * OUT_FEAT);
        const float4* as4   = reinterpret_cast<const float4*>(attn_w);
        const float4* at4   = reinterpret_cast<const float4*>(attn_w + OUT_FEAT);

        float4 w0 = wrow4[lane];
        float4 w1 = wrow4[32 + lane];
        float acc_s = dot4(w0, as4[lane]) + dot4(w1, as4[32 + lane]);
        float acc_t = dot4(w0, at4[lane]) + dot4(w1, at4[32 + lane]);
#pragma unroll
        for (int off = 16; off > 0; off >>= 1) {
            acc_s += __shfl_xor_sync(0xffffffffu, acc_s, off);
            acc_t += __shfl_xor_sync(0xffffffffu, acc_t, off);
        }
        if (lane == 0) {
            reinterpret_cast<float*>(g_w_src4)[gw] = acc_s;
            reinterpret_cast<float*>(g_w_tgt4)[gw] = acc_t;
        }
    }

    grid_sync(nblocks);

    // Stage w vectors into shared (4 KB)
    for (int i = tid; i < IN_FEAT / 4; i += 256) {
        sh_ws[i] = g_w_src4[i];
        sh_wt[i] = g_w_tgt4[i];
    }
    __syncthreads();

    // ---------------- Phase B: node scores, warp-level work stealing -------
    for (;;) {
        unsigned base;
        if (lane == 0) base = atomicAdd(&g_node_ctr, NODE_CHUNK);
        base = __shfl_sync(0xffffffffu, base, 0);
        if (base >= N_NODES) break;
        unsigned end = base + NODE_CHUNK;
        if (end > N_NODES) end = N_NODES;

        for (unsigned node = base; node < end; node++) {
            const float4* h4 = reinterpret_cast<const float4*>(h + (size_t)node * IN_FEAT);

            float4 hv0 = h4[lane];
            float4 hv1 = h4[32 + lane];
            float4 hv2 = h4[64 + lane];
            float4 hv3 = h4[96 + lane];

            // Warm L2 with the edge lines this node index maps to
            // (node*32 edges of 4B = one 128B line per stream; covers all
            //  12.8 MB of edge_list across the 50000 node iterations).
            if (lane == 0) {
                prefetch_l2(edge_list + (size_t)node * 32);
                prefetch_l2(edge_list + N_EDGES + (size_t)node * 32);
            }

            float acc_s = dot4(hv0, sh_ws[lane])      + dot4(hv1, sh_ws[32 + lane]) +
                          dot4(hv2, sh_ws[64 + lane]) + dot4(hv3, sh_ws[96 + lane]);
            float acc_t = dot4(hv0, sh_wt[lane])      + dot4(hv1, sh_wt[32 + lane]) +
                          dot4(hv2, sh_wt[64 + lane]) + dot4(hv3, sh_wt[96 + lane]);

            // Split-half reduction: lo 16 lanes reduce s, hi 16 reduce t.
            float os = __shfl_xor_sync(0xffffffffu, acc_s, 16);
            float ot = __shfl_xor_sync(0xffffffffu, acc_t, 16);
            float v = (lane < 16) ? (acc_s + os) : (acc_t + ot);
#pragma unroll
            for (int off = 8; off > 0; off >>= 1)
                v += __shfl_xor_sync(0xffffffffu, v, off);
            if (lane == 0)  g_s_src[node] = v;
            if (lane == 16) g_s_tgt[node] = v;
        }
    }

    grid_sync(nblocks);

    // ---------------- Phase C: edge gather, warp-level work stealing -------
    const int n4 = N_EDGES / 4;
    const int4*  src4 = reinterpret_cast<const int4*>(edge_list);
    const int4*  tgt4 = reinterpret_cast<const int4*>(edge_list + N_EDGES);
    float4*      out4 = reinterpret_cast<float4*>(out);

    for (;;) {
        unsigned base;
        if (lane == 0) base = atomicAdd(&g_edge_ctr, EDGE_CHUNK);
        base = __shfl_sync(0xffffffffu, base, 0);
        if (base >= (unsigned)n4) break;
        unsigned end = base + EDGE_CHUNK;
        if (end > (unsigned)n4) end = (unsigned)n4;

        for (unsigned k4 = base + lane; k4 < end; k4 += 32) {
            int4 s = src4[k4];
            int4 t = tgt4[k4];

            float e0 = __ldg(&g_s_src[s.x]) + __ldg(&g_s_tgt[t.x]);
            float e1 = __ldg(&g_s_src[s.y]) + __ldg(&g_s_tgt[t.y]);
            float e2 = __ldg(&g_s_src[s.z]) + __ldg(&g_s_tgt[t.z]);
            float e3 = __ldg(&g_s_src[s.w]) + __ldg(&g_s_tgt[t.w]);

            float4 r;
            r.x = (e0 > 0.f) ? e0 : ALPHA * e0;
            r.y = (e1 > 0.f) ? e1 : ALPHA * e1;
            r.z = (e2 > 0.f) ? e2 : ALPHA * e2;
            r.w = (e3 > 0.f) ? e3 : ALPHA * e3;
            out4[k4] = r;
        }
    }
}

// ---------------------------------------------------------------------------
extern "C" void kernel_launch(void* const* d_in, const int* in_sizes, int n_in,
                              void* d_out, int out_size) {
    const float* h         = (const float*)d_in[0];
    const int*   edge_list = (const int*)d_in[1];
    const float* W         = (const float*)d_in[2];
    const float* attn_w    = (const float*)d_in[3];
    float* out = (float*)d_out;

    int dev = 0;
    cudaGetDevice(&dev);
    int sms = 148;
    cudaDeviceGetAttribute(&sms, cudaDevAttrMultiProcessorCount, dev);
    int occ = 1;
    cudaOccupancyMaxActiveBlocksPerMultiprocessor(&occ, fused_gat_kernel, 256, 0);
    if (occ < 1) occ = 1;
    int nblocks = sms * occ;           // exactly one co-resident wave
    if (nblocks < 64) nblocks = 64;    // phase A needs >= 512 warps

    fused_gat_kernel<<<nblocks, 256>>>(h, edge_list, W, attn_w, out, nblocks);
}

// round 13
// speedup vs baseline: 1.6392x; 1.6392x over previous
#include <cuda_runtime.h>
#include <cstdint>

#define N_NODES 50000
#define IN_FEAT 512
#define OUT_FEAT 256
#define N_EDGES 1600000
#define ALPHA 0.2f

// Scratch (allocation-free rule: __device__ globals).
__device__ float4 g_w_src4[IN_FEAT / 4];
__device__ float4 g_w_tgt4[IN_FEAT / 4];
__device__ float g_s_src[N_NODES];
__device__ float g_s_tgt[N_NODES];

// Monotonic-ticket grid barrier (no reset; safe across graph replays).
__device__ unsigned g_bar = 0;

__device__ __forceinline__ float dot4(float4 a, float4 b) {
    return a.x * b.x + a.y * b.y + a.z * b.z + a.w * b.w;
}

__device__ __forceinline__ void grid_sync(unsigned nblocks) {
    __syncthreads();
    if (threadIdx.x == 0) {
        __threadfence();
        unsigned ticket = atomicAdd(&g_bar, 1u);
        unsigned target = (ticket / nblocks + 1u) * nblocks;
        while (*(volatile unsigned*)&g_bar < target) { }
        __threadfence();
    }
    __syncthreads();
}

// ---------------------------------------------------------------------------
// Kernel 1: phase A (w = W @ a) -> grid barrier -> phase B (node scores).
// Phase bodies FROZEN from the 36.0us R5 kernel (60 regs, 4 blocks/SM).
// ---------------------------------------------------------------------------
__global__ __launch_bounds__(256) void ab_kernel(
    const float* __restrict__ h,
    const float* __restrict__ W,
    const float* __restrict__ attn_w,
    int nblocks)
{
    __shared__ float4 sh_ws[IN_FEAT / 4];
    __shared__ float4 sh_wt[IN_FEAT / 4];

    const int tid  = threadIdx.x;
    const int lane = tid & 31;
    const int wid  = tid >> 5;
    const int gw   = blockIdx.x * 8 + wid;
    const int nwarps = nblocks * 8;

    // ---------------- Phase A ----------------------------------------------
    if (gw < IN_FEAT) {
        const float4* wrow4 = reinterpret_cast<const float4*>(W + (size_t)gw * OUT_FEAT);
        const float4* as4   = reinterpret_cast<const float4*>(attn_w);
        const float4* at4   = reinterpret_cast<const float4*>(attn_w + OUT_FEAT);

        float4 w0 = wrow4[lane];
        float4 w1 = wrow4[32 + lane];
        float acc_s = dot4(w0, as4[lane]) + dot4(w1, as4[32 + lane]);
        float acc_t = dot4(w0, at4[lane]) + dot4(w1, at4[32 + lane]);
#pragma unroll
        for (int off = 16; off > 0; off >>= 1) {
            acc_s += __shfl_xor_sync(0xffffffffu, acc_s, off);
            acc_t += __shfl_xor_sync(0xffffffffu, acc_t, off);
        }
        if (lane == 0) {
            reinterpret_cast<float*>(g_w_src4)[gw] = acc_s;
            reinterpret_cast<float*>(g_w_tgt4)[gw] = acc_t;
        }
    }

    grid_sync(nblocks);

    // Stage w vectors into shared (4 KB)
    for (int i = tid; i < IN_FEAT / 4; i += 256) {
        sh_ws[i] = g_w_src4[i];
        sh_wt[i] = g_w_tgt4[i];
    }
    __syncthreads();

    // ---------------- Phase B: warp per node, grid-stride ------------------
    for (int node = gw; node < N_NODES; node += nwarps) {
        const float4* h4 = reinterpret_cast<const float4*>(h + (size_t)node * IN_FEAT);

        float4 hv0 = h4[lane];
        float4 hv1 = h4[32 + lane];
        float4 hv2 = h4[64 + lane];
        float4 hv3 = h4[96 + lane];

        float acc_s = dot4(hv0, sh_ws[lane])      + dot4(hv1, sh_ws[32 + lane]) +
                      dot4(hv2, sh_ws[64 + lane]) + dot4(hv3, sh_ws[96 + lane]);
        float acc_t = dot4(hv0, sh_wt[lane])      + dot4(hv1, sh_wt[32 + lane]) +
                      dot4(hv2, sh_wt[64 + lane]) + dot4(hv3, sh_wt[96 + lane]);

        // Split-half reduction: lo 16 lanes reduce s, hi 16 reduce t.
        float os = __shfl_xor_sync(0xffffffffu, acc_s, 16);
        float ot = __shfl_xor_sync(0xffffffffu, acc_t, 16);
        float v = (lane < 16) ? (acc_s + os) : (acc_t + ot);
#pragma unroll
        for (int off = 8; off > 0; off >>= 1)
            v += __shfl_xor_sync(0xffffffffu, v, off);
        if (lane == 0)  g_s_src[node] = v;
        if (lane == 16) g_s_tgt[node] = v;
    }
}

// ---------------------------------------------------------------------------
// Kernel 2: phase C standalone. Exact-fit grid, one int4-group (4 edges) per
// thread, no loop. Low regs -> ~8 blocks/SM -> 2048 threads/SM (100% occ)
// -> 2x outstanding gathers vs the fused version. Full 228 KB L1 for the
// 400 KB score working set.
// ---------------------------------------------------------------------------
__global__ __launch_bounds__(256) void edge_kernel(
    const int* __restrict__ edge_list,
    float*     __restrict__ out)
{
    const int k4 = blockIdx.x * 256 + threadIdx.x;
    if (k4 >= N_EDGES / 4) return;

    int4 s = reinterpret_cast<const int4*>(edge_list)[k4];
    int4 t = reinterpret_cast<const int4*>(edge_list + N_EDGES)[k4];

    float e0 = __ldg(&g_s_src[s.x]) + __ldg(&g_s_tgt[t.x]);
    float e1 = __ldg(&g_s_src[s.y]) + __ldg(&g_s_tgt[t.y]);
    float e2 = __ldg(&g_s_src[s.z]) + __ldg(&g_s_tgt[t.z]);
    float e3 = __ldg(&g_s_src[s.w]) + __ldg(&g_s_tgt[t.w]);

    float4 r;
    r.x = (e0 > 0.f) ? e0 : ALPHA * e0;
    r.y = (e1 > 0.f) ? e1 : ALPHA * e1;
    r.z = (e2 > 0.f) ? e2 : ALPHA * e2;
    r.w = (e3 > 0.f) ? e3 : ALPHA * e3;
    reinterpret_cast<float4*>(out)[k4] = r;
}

// ---------------------------------------------------------------------------
extern "C" void kernel_launch(void* const* d_in, const int* in_sizes, int n_in,
                              void* d_out, int out_size) {
    const float* h         = (const float*)d_in[0];
    const int*   edge_list = (const int*)d_in[1];
    const float* W         = (const float*)d_in[2];
    const float* attn_w    = (const float*)d_in[3];
    float* out = (float*)d_out;

    int dev = 0;
    cudaGetDevice(&dev);
    int sms = 148;
    cudaDeviceGetAttribute(&sms, cudaDevAttrMultiProcessorCount, dev);
    int occ = 1;
    cudaOccupancyMaxActiveBlocksPerMultiprocessor(&occ, ab_kernel, 256, 0);
    if (occ < 1) occ = 1;
    int nblocks_ab = sms * occ;            // exactly one co-resident wave
    if (nblocks_ab < 64) nblocks_ab = 64;  // phase A needs >= 512 warps

    ab_kernel<<<nblocks_ab, 256>>>(h, W, attn_w, nblocks_ab);

    // C: exact fit, 400000 int4-groups / 256 = 1562.5 -> 1563 blocks
    edge_kernel<<<(N_EDGES / 4 + 255) / 256, 256>>>(edge_list, out);
}